// round 2
// baseline (speedup 1.0000x reference)
#include <cuda_runtime.h>
#include <math.h>

#define NN 100000
#define NE 1600000
#define IND 256
#define HIDD 128
#define OUTD 32
#define NEG_SLOPE 0.2f

// ---------------- static scratch (no runtime allocation allowed) ----------------
__device__ float g_xs1[(size_t)NN * HIDD];
__device__ float g_h1[(size_t)NN * HIDD];
__device__ float g_xs3[(size_t)NN * HIDD];
__device__ float g_h3[(size_t)NN * HIDD];
__device__ float g_as1[NN];
__device__ float g_ad1[NN];
__device__ float g_wbuf[NE];
__device__ int   g_deg[NN];
__device__ int   g_off[NN];
__device__ int   g_cur[NN];
__device__ int   g_esrc[NE];
__device__ int   g_stmp[NN];
__device__ int   g_bsum[128];
__device__ int   g_boff[128];
__device__ float g_W1T[HIDD * IND];
__device__ float g_W2T[OUTD * HIDD];

// ---------------- CSR build ----------------
__global__ void k_zero_deg() {
    int i = blockIdx.x * blockDim.x + threadIdx.x;
    if (i < NN) g_deg[i] = 0;
}

__global__ void k_hist(const int* __restrict__ dst) {
    int e = blockIdx.x * blockDim.x + threadIdx.x;
    if (e < NE) atomicAdd(&g_deg[dst[e]], 1);
}

// inclusive block scan (1024-wide chunks)
__global__ void k_scan1() {
    __shared__ int sm[1024];
    int b = blockIdx.x, t = threadIdx.x;
    int i = b * 1024 + t;
    int v = (i < NN) ? g_deg[i] : 0;
    sm[t] = v;
    __syncthreads();
    for (int ofs = 1; ofs < 1024; ofs <<= 1) {
        int x = (t >= ofs) ? sm[t - ofs] : 0;
        __syncthreads();
        sm[t] += x;
        __syncthreads();
    }
    if (i < NN) g_stmp[i] = sm[t];
    if (t == 1023) g_bsum[b] = sm[1023];
}

__global__ void k_scan2(int nblk) {
    int run = 0;
    for (int b = 0; b < nblk; b++) { g_boff[b] = run; run += g_bsum[b]; }
}

__global__ void k_scan3() {
    int i = blockIdx.x * blockDim.x + threadIdx.x;
    if (i < NN) {
        int off = g_stmp[i] - g_deg[i] + g_boff[i >> 10]; // exclusive
        g_off[i] = off;
        g_cur[i] = off;
    }
}

__global__ void k_scatter(const int* __restrict__ src,
                          const int* __restrict__ dst) {
    int e = blockIdx.x * blockDim.x + threadIdx.x;
    if (e < NE) {
        int d = dst[e];
        int pos = atomicAdd(&g_cur[d], 1);
        g_esrc[pos] = src[e];
    }
}

// ---------------- weight transposes ----------------
__global__ void k_transpose_W1(const float* __restrict__ W1) {
    int idx = blockIdx.x * blockDim.x + threadIdx.x; // IND*HIDD
    if (idx < IND * HIDD) {
        int i = idx / HIDD, h = idx % HIDD;
        g_W1T[h * IND + i] = W1[i * HIDD + h];
    }
}

__global__ void k_transpose_W2(const float* __restrict__ W2) {
    int idx = blockIdx.x * blockDim.x + threadIdx.x; // HIDD*OUTD
    if (idx < HIDD * OUTD) {
        int h = idx / OUTD, o = idx % OUTD;
        g_W2T[o * HIDD + h] = W2[h * OUTD + o];
    }
}

// ---------------- GEMM: C[M,N] = A[M,K] * B[K,N]  (N multiple of BN, K multiple of 8) ----------------
template <int BN, int NT>
__global__ void k_gemm(const float* __restrict__ A, const float* __restrict__ B,
                       float* __restrict__ C, int M, int N, int K) {
    const int BM = 128, BK = 8, TM = 8, TN = 8;
    __shared__ float As[BK][BM + 4];
    __shared__ float Bs[BK][BN];
    int tid = threadIdx.x;
    int tc = tid % (BN / TN);
    int tr = tid / (BN / TN);
    int m0 = blockIdx.y * BM;
    int n0 = blockIdx.x * BN;

    float acc[TM][TN];
#pragma unroll
    for (int r = 0; r < TM; r++)
#pragma unroll
        for (int c = 0; c < TN; c++) acc[r][c] = 0.f;

    for (int k0 = 0; k0 < K; k0 += BK) {
        // load A tile (BM x BK) transposed into As[k][m]
#pragma unroll
        for (int i = 0; i < (BM * BK / 4) / NT; i++) {
            int t = tid + i * NT;
            int m = t >> 1;
            int kk = (t & 1) * 4;
            float4 v = make_float4(0.f, 0.f, 0.f, 0.f);
            if (m0 + m < M)
                v = *(const float4*)&A[(size_t)(m0 + m) * K + k0 + kk];
            As[kk + 0][m] = v.x;
            As[kk + 1][m] = v.y;
            As[kk + 2][m] = v.z;
            As[kk + 3][m] = v.w;
        }
        // load B tile (BK x BN)
#pragma unroll
        for (int i = 0; i < (BK * BN / 4) / NT; i++) {
            int t = tid + i * NT;
            int kk = t / (BN / 4);
            int nn = (t % (BN / 4)) * 4;
            *(float4*)&Bs[kk][nn] = *(const float4*)&B[(size_t)(k0 + kk) * N + n0 + nn];
        }
        __syncthreads();
#pragma unroll
        for (int kk = 0; kk < BK; kk++) {
            float a[TM], b[TN];
#pragma unroll
            for (int r = 0; r < TM; r++) a[r] = As[kk][tr * TM + r];
#pragma unroll
            for (int c = 0; c < TN; c++) b[c] = Bs[kk][tc * TN + c];
#pragma unroll
            for (int r = 0; r < TM; r++)
#pragma unroll
                for (int c = 0; c < TN; c++) acc[r][c] += a[r] * b[c];
        }
        __syncthreads();
    }

#pragma unroll
    for (int r = 0; r < TM; r++) {
        int m = m0 + tr * TM + r;
        if (m < M) {
#pragma unroll
            for (int c = 0; c < TN; c += 4) {
                float4 v = make_float4(acc[r][c], acc[r][c + 1], acc[r][c + 2], acc[r][c + 3]);
                *(float4*)&C[(size_t)m * N + n0 + tc * TN + c] = v;
            }
        }
    }
}

// ---------------- per-node attention logits: as1=xs1@a_src, ad1=xs1@a_dst ----------------
__global__ void k_logits(const float* __restrict__ a_src, const float* __restrict__ a_dst) {
    int warp = (blockIdx.x * blockDim.x + threadIdx.x) >> 5;
    int lane = threadIdx.x & 31;
    if (warp >= NN) return;
    float4 x4 = *(const float4*)&g_xs1[(size_t)warp * HIDD + lane * 4];
    float4 s4 = *(const float4*)&a_src[lane * 4];
    float4 d4 = *(const float4*)&a_dst[lane * 4];
    float ds = x4.x * s4.x + x4.y * s4.y + x4.z * s4.z + x4.w * s4.w;
    float dd = x4.x * d4.x + x4.y * d4.y + x4.z * d4.z + x4.w * d4.w;
#pragma unroll
    for (int o = 16; o > 0; o >>= 1) {
        ds += __shfl_xor_sync(0xffffffffu, ds, o);
        dd += __shfl_xor_sync(0xffffffffu, dd, o);
    }
    if (lane == 0) {
        g_as1[warp] = ds;
        g_ad1[warp] = dd;
    }
}

// ---------------- segment softmax: normalized attention weight per edge (CSR order) ----------------
__global__ void k_attention() {
    int warp = (blockIdx.x * blockDim.x + threadIdx.x) >> 5;
    int lane = threadIdx.x & 31;
    if (warp >= NN) return;
    int off = g_off[warp];
    int d = g_deg[warp];
    if (d == 0) return;
    float adi = g_ad1[warp];

    float m = -INFINITY;
    for (int k = lane; k < d; k += 32) {
        int s = g_esrc[off + k];
        float v = g_as1[s] + adi;
        v = (v > 0.f) ? v : NEG_SLOPE * v;
        g_wbuf[off + k] = v;
        m = fmaxf(m, v);
    }
#pragma unroll
    for (int o = 16; o > 0; o >>= 1) m = fmaxf(m, __shfl_xor_sync(0xffffffffu, m, o));

    float S = 0.f;
    for (int k = lane; k < d; k += 32) {
        float w = expf(g_wbuf[off + k] - m);
        g_wbuf[off + k] = w;
        S += w;
    }
#pragma unroll
    for (int o = 16; o > 0; o >>= 1) S += __shfl_xor_sync(0xffffffffu, S, o);

    float inv = 1.f / S;
    for (int k = lane; k < d; k += 32) g_wbuf[off + k] *= inv;
}

// ---------------- weighted gather + ELU: out[i] = elu(sum_e a_e * in[src_e]) ----------------
__global__ void k_gather_elu(const float* __restrict__ in, float* __restrict__ out) {
    int warp = (blockIdx.x * blockDim.x + threadIdx.x) >> 5;
    int lane = threadIdx.x & 31;
    if (warp >= NN) return;
    int off = g_off[warp];
    int d = g_deg[warp];
    float4 acc = make_float4(0.f, 0.f, 0.f, 0.f);

    if (d > 0) {
        float a = g_wbuf[off];
        int s = g_esrc[off];
        for (int k = 0; k < d; k++) {
            float an = 0.f;
            int sn = 0;
            if (k + 1 < d) {
                an = g_wbuf[off + k + 1];
                sn = g_esrc[off + k + 1];
            }
            const float4 v = *(const float4*)&in[(size_t)s * HIDD + lane * 4];
            acc.x += a * v.x;
            acc.y += a * v.y;
            acc.z += a * v.z;
            acc.w += a * v.w;
            a = an;
            s = sn;
        }
    }
    // ELU (alpha = 1)
    acc.x = (acc.x > 0.f) ? acc.x : expm1f(acc.x);
    acc.y = (acc.y > 0.f) ? acc.y : expm1f(acc.y);
    acc.z = (acc.z > 0.f) ? acc.z : expm1f(acc.z);
    acc.w = (acc.w > 0.f) ? acc.w : expm1f(acc.w);
    *(float4*)&out[(size_t)warp * HIDD + lane * 4] = acc;
}

// ---------------- launcher ----------------
extern "C" void kernel_launch(void* const* d_in, const int* in_sizes, int n_in,
                              void* d_out, int out_size) {
    const float* x = (const float*)d_in[0];       // [NN, IND]
    const float* W1 = (const float*)d_in[1];      // [IND, HIDD]
    const float* a_src = (const float*)d_in[2];   // [HIDD]
    const float* a_dst = (const float*)d_in[3];   // [HIDD]
    const float* W2 = (const float*)d_in[4];      // [HIDD, OUTD]
    const int* eidx = (const int*)d_in[5];        // [2, NE] int32 (JAX x64 disabled)
    const int* src = eidx;
    const int* dst = eidx + NE;

    float* h2 = (float*)d_out;                       // [NN, OUTD]
    float* h4 = (float*)d_out + (size_t)NN * OUTD;   // [NN, IND]

    // device-global scratch addresses (host-side symbol queries; no allocation)
    float *p_xs1, *p_h1, *p_xs3, *p_h3, *p_W1T, *p_W2T;
    cudaGetSymbolAddress((void**)&p_xs1, g_xs1);
    cudaGetSymbolAddress((void**)&p_h1, g_h1);
    cudaGetSymbolAddress((void**)&p_xs3, g_xs3);
    cudaGetSymbolAddress((void**)&p_h3, g_h3);
    cudaGetSymbolAddress((void**)&p_W1T, g_W1T);
    cudaGetSymbolAddress((void**)&p_W2T, g_W2T);

    const int NBLK = (NN + 1023) / 1024; // 98

    // --- CSR build ---
    k_zero_deg<<<(NN + 255) / 256, 256>>>();
    k_hist<<<(NE + 255) / 256, 256>>>(dst);
    k_scan1<<<NBLK, 1024>>>();
    k_scan2<<<1, 1>>>(NBLK);
    k_scan3<<<(NN + 255) / 256, 256>>>();
    k_scatter<<<(NE + 255) / 256, 256>>>(src, dst);

    // --- weight transposes ---
    k_transpose_W1<<<(IND * HIDD + 255) / 256, 256>>>(W1);
    k_transpose_W2<<<(HIDD * OUTD + 255) / 256, 256>>>(W2);

    const int GY = (NN + 127) / 128; // 782
    const int WG = (NN * 32 + 255) / 256; // warp-per-node grid (12500)

    // --- G1: xs1 = x @ W1 ---
    k_gemm<128, 256><<<dim3(1, GY), 256>>>(x, W1, p_xs1, NN, HIDD, IND);

    // --- per-node logits + softmax weights (shared by both aggregations) ---
    k_logits<<<WG, 256>>>(a_src, a_dst);
    k_attention<<<WG, 256>>>();

    // --- agg1: h1 = elu(A * xs1) ---
    k_gather_elu<<<WG, 256>>>(p_xs1, p_h1);

    // --- G2: h2 = h1 @ W2  (output #1) ---
    k_gemm<32, 64><<<dim3(1, GY), 64>>>(p_h1, W2, h2, NN, OUTD, HIDD);

    // --- G3: xs3 = h2 @ W2^T ---
    k_gemm<128, 256><<<dim3(1, GY), 256>>>(h2, p_W2T, p_xs3, NN, HIDD, OUTD);

    // --- agg2: h3 = elu(A * xs3) ---
    k_gather_elu<<<WG, 256>>>(p_xs3, p_h3);

    // --- G4: h4 = h3 @ W1^T  (output #2) ---
    k_gemm<128, 256><<<dim3(2, GY), 256>>>(p_h3, p_W1T, h4, NN, IND, HIDD);
}

// round 5
// speedup vs baseline: 1.3858x; 1.3858x over previous
#include <cuda_runtime.h>
#include <cuda_bf16.h>
#include <cstdint>
#include <math.h>

#define NN 100000
#define NE 1600000
#define IND 256
#define HIDD 128
#define OUTD 32
#define NEG_SLOPE 0.2f

// ---------------- static scratch (no runtime allocation allowed) ----------------
__device__ float g_xs1[(size_t)NN * HIDD];
__device__ float g_h1[(size_t)NN * HIDD];
__device__ float g_xs3[(size_t)NN * HIDD];
__device__ float g_h3[(size_t)NN * HIDD];
__device__ float g_as1[NN];
__device__ float g_ad1[NN];
__device__ float g_wbuf[NE];
__device__ int   g_deg[NN];
__device__ int   g_off[NN];
__device__ int   g_cur[NN];
__device__ int   g_esrc[NE];
__device__ int   g_stmp[NN];
__device__ int   g_bsum[128];
__device__ int   g_boff[128];
__device__ float g_W1T[HIDD * IND];
__device__ float g_W2T[OUTD * HIDD];

// ---------------- CSR build ----------------
__global__ void k_zero_deg() {
    int i = blockIdx.x * blockDim.x + threadIdx.x;
    if (i < NN) g_deg[i] = 0;
}

__global__ void k_hist(const int* __restrict__ dst) {
    int e = blockIdx.x * blockDim.x + threadIdx.x;
    if (e < NE) atomicAdd(&g_deg[dst[e]], 1);
}

// inclusive block scan (1024-wide chunks)
__global__ void k_scan1() {
    __shared__ int sm[1024];
    int b = blockIdx.x, t = threadIdx.x;
    int i = b * 1024 + t;
    int v = (i < NN) ? g_deg[i] : 0;
    sm[t] = v;
    __syncthreads();
    for (int ofs = 1; ofs < 1024; ofs <<= 1) {
        int x = (t >= ofs) ? sm[t - ofs] : 0;
        __syncthreads();
        sm[t] += x;
        __syncthreads();
    }
    if (i < NN) g_stmp[i] = sm[t];
    if (t == 1023) g_bsum[b] = sm[1023];
}

// parallel scan of the 98 block sums (1 block, 128 threads)
__global__ void k_scan2() {
    __shared__ int sm[128];
    int t = threadIdx.x;
    int v = (t < 98) ? g_bsum[t] : 0;
    sm[t] = v;
    __syncthreads();
    for (int ofs = 1; ofs < 128; ofs <<= 1) {
        int x = (t >= ofs) ? sm[t - ofs] : 0;
        __syncthreads();
        sm[t] += x;
        __syncthreads();
    }
    if (t < 98) g_boff[t] = sm[t] - v; // exclusive
}

__global__ void k_scan3() {
    int i = blockIdx.x * blockDim.x + threadIdx.x;
    if (i < NN) {
        int off = g_stmp[i] - g_deg[i] + g_boff[i >> 10]; // exclusive
        g_off[i] = off;
        g_cur[i] = off;
    }
}

__global__ void k_scatter(const int* __restrict__ src,
                          const int* __restrict__ dst) {
    int e = blockIdx.x * blockDim.x + threadIdx.x;
    if (e < NE) {
        int d = dst[e];
        int pos = atomicAdd(&g_cur[d], 1);
        g_esrc[pos] = src[e];
    }
}

// ---------------- weight transposes ----------------
__global__ void k_transpose_W1(const float* __restrict__ W1) {
    int idx = blockIdx.x * blockDim.x + threadIdx.x; // IND*HIDD
    if (idx < IND * HIDD) {
        int i = idx / HIDD, h = idx % HIDD;
        g_W1T[h * IND + i] = W1[i * HIDD + h];
    }
}

__global__ void k_transpose_W2(const float* __restrict__ W2) {
    int idx = blockIdx.x * blockDim.x + threadIdx.x; // HIDD*OUTD
    if (idx < HIDD * OUTD) {
        int h = idx / OUTD, o = idx % OUTD;
        g_W2T[o * HIDD + h] = W2[h * OUTD + o];
    }
}

// ---------------- tensor-core GEMM (bf16 split, fp32-accurate) ----------------
__device__ __forceinline__ void ldsm_x4(unsigned (&r)[4], unsigned addr) {
    asm volatile("ldmatrix.sync.aligned.m8n8.x4.shared.b16 {%0,%1,%2,%3}, [%4];"
                 : "=r"(r[0]), "=r"(r[1]), "=r"(r[2]), "=r"(r[3]) : "r"(addr));
}
__device__ __forceinline__ void ldsm_x4_t(unsigned (&r)[4], unsigned addr) {
    asm volatile("ldmatrix.sync.aligned.m8n8.x4.trans.shared.b16 {%0,%1,%2,%3}, [%4];"
                 : "=r"(r[0]), "=r"(r[1]), "=r"(r[2]), "=r"(r[3]) : "r"(addr));
}
__device__ __forceinline__ void mma_bf16(float (&c)[4], const unsigned (&a)[4],
                                         const unsigned (&b)[2]) {
    asm volatile(
        "mma.sync.aligned.m16n8k16.row.col.f32.bf16.bf16.f32 "
        "{%0,%1,%2,%3}, {%4,%5,%6,%7}, {%8,%9}, {%0,%1,%2,%3};"
        : "+f"(c[0]), "+f"(c[1]), "+f"(c[2]), "+f"(c[3])
        : "r"(a[0]), "r"(a[1]), "r"(a[2]), "r"(a[3]), "r"(b[0]), "r"(b[1]));
}

__device__ __forceinline__ void split_store(__nv_bfloat16* H, __nv_bfloat16* L,
                                            int idx, float v) {
    __nv_bfloat16 h = __float2bfloat16(v);
    float lo = v - __bfloat162float(h);
    H[idx] = h;
    L[idx] = __float2bfloat16(lo);
}

// C[M,N] = A[M,K] @ B[K,N], fp32 in/out. N % BN == 0, K % 32 == 0. 256 threads.
template <int MWARPS, int NWARPS, int MFRAG, int NFRAG>
__global__ __launch_bounds__(256, 1) void k_gemm_tc(const float* __restrict__ A,
                                                    const float* __restrict__ B,
                                                    float* __restrict__ C,
                                                    int M, int N, int K) {
    constexpr int BM = MWARPS * MFRAG * 16;
    constexpr int BN = NWARPS * NFRAG * 8;
    constexpr int BK = 32;
    constexpr int SA = BK + 8;   // bf16 elems per A smem row
    constexpr int SB = BN + 8;   // bf16 elems per B smem row

    __shared__ alignas(16) __nv_bfloat16 Ah[BM * SA];
    __shared__ alignas(16) __nv_bfloat16 Al[BM * SA];
    __shared__ alignas(16) __nv_bfloat16 Bh[BK * SB];
    __shared__ alignas(16) __nv_bfloat16 Bl[BK * SB];

    const int tid = threadIdx.x;
    const int warp = tid >> 5, lane = tid & 31;
    const int wm = warp % MWARPS, wn = warp / MWARPS;
    const int m0 = blockIdx.y * BM, n0 = blockIdx.x * BN;

    const unsigned sAh = (unsigned)__cvta_generic_to_shared(Ah);
    const unsigned sAl = (unsigned)__cvta_generic_to_shared(Al);
    const unsigned sBh = (unsigned)__cvta_generic_to_shared(Bh);
    const unsigned sBl = (unsigned)__cvta_generic_to_shared(Bl);

    float acc[MFRAG][NFRAG][4];
#pragma unroll
    for (int f = 0; f < MFRAG; f++)
#pragma unroll
        for (int g = 0; g < NFRAG; g++)
#pragma unroll
            for (int i = 0; i < 4; i++) acc[f][g][i] = 0.f;

    for (int k0 = 0; k0 < K; k0 += BK) {
        // --- A tile (BM x BK fp32) -> split bf16 smem ---
#pragma unroll
        for (int i = 0; i < (BM * BK / 4) / 256; i++) {
            int t = tid + i * 256;
            int r = t / (BK / 4);
            int c = (t % (BK / 4)) * 4;
            float4 v = make_float4(0.f, 0.f, 0.f, 0.f);
            if (m0 + r < M) v = *(const float4*)&A[(size_t)(m0 + r) * K + k0 + c];
            int idx = r * SA + c;
            split_store(Ah, Al, idx + 0, v.x);
            split_store(Ah, Al, idx + 1, v.y);
            split_store(Ah, Al, idx + 2, v.z);
            split_store(Ah, Al, idx + 3, v.w);
        }
        // --- B tile (BK x BN fp32) -> split bf16 smem ---
#pragma unroll
        for (int i = 0; i < (BK * BN / 4) / 256; i++) {
            int t = tid + i * 256;
            int r = t / (BN / 4);
            int c = (t % (BN / 4)) * 4;
            float4 v = *(const float4*)&B[(size_t)(k0 + r) * N + n0 + c];
            int idx = r * SB + c;
            split_store(Bh, Bl, idx + 0, v.x);
            split_store(Bh, Bl, idx + 1, v.y);
            split_store(Bh, Bl, idx + 2, v.z);
            split_store(Bh, Bl, idx + 3, v.w);
        }
        __syncthreads();

#pragma unroll
        for (int ks = 0; ks < 2; ks++) {
            unsigned ah[MFRAG][4], al[MFRAG][4];
#pragma unroll
            for (int f = 0; f < MFRAG; f++) {
                int row = wm * (MFRAG * 16) + f * 16 + (lane & 15);
                int col = ks * 16 + (lane >> 4) * 8;
                unsigned off = (unsigned)(row * SA + col) * 2u;
                ldsm_x4(ah[f], sAh + off);
                ldsm_x4(al[f], sAl + off);
            }
            unsigned bhf[NFRAG][2], blf[NFRAG][2];
#pragma unroll
            for (int nb = 0; nb < NFRAG / 2; nb++) {
                int krow = ks * 16 + (lane & 7) + ((lane >> 3) & 1) * 8;
                int col = wn * (NFRAG * 8) + nb * 16 + ((lane >> 4) & 1) * 8;
                unsigned off = (unsigned)(krow * SB + col) * 2u;
                unsigned r4[4];
                ldsm_x4_t(r4, sBh + off);
                bhf[2 * nb][0] = r4[0]; bhf[2 * nb][1] = r4[1];
                bhf[2 * nb + 1][0] = r4[2]; bhf[2 * nb + 1][1] = r4[3];
                ldsm_x4_t(r4, sBl + off);
                blf[2 * nb][0] = r4[0]; blf[2 * nb][1] = r4[1];
                blf[2 * nb + 1][0] = r4[2]; blf[2 * nb + 1][1] = r4[3];
            }
#pragma unroll
            for (int f = 0; f < MFRAG; f++)
#pragma unroll
                for (int g = 0; g < NFRAG; g++) {
                    mma_bf16(acc[f][g], ah[f], bhf[g]);
                    mma_bf16(acc[f][g], al[f], bhf[g]);
                    mma_bf16(acc[f][g], ah[f], blf[g]);
                }
        }
        __syncthreads();
    }

    // --- store C ---
#pragma unroll
    for (int f = 0; f < MFRAG; f++) {
#pragma unroll
        for (int g = 0; g < NFRAG; g++) {
            int r0 = m0 + wm * (MFRAG * 16) + f * 16 + (lane >> 2);
            int cc = n0 + wn * (NFRAG * 8) + g * 8 + (lane & 3) * 2;
            if (r0 < M) {
                float2 v = make_float2(acc[f][g][0], acc[f][g][1]);
                *(float2*)&C[(size_t)r0 * N + cc] = v;
            }
            if (r0 + 8 < M) {
                float2 v = make_float2(acc[f][g][2], acc[f][g][3]);
                *(float2*)&C[(size_t)(r0 + 8) * N + cc] = v;
            }
        }
    }
}

// ---------------- per-node attention logits: as1=xs1@a_src, ad1=xs1@a_dst ----------------
__global__ void k_logits(const float* __restrict__ a_src, const float* __restrict__ a_dst) {
    int warp = (blockIdx.x * blockDim.x + threadIdx.x) >> 5;
    int lane = threadIdx.x & 31;
    if (warp >= NN) return;
    float4 x4 = *(const float4*)&g_xs1[(size_t)warp * HIDD + lane * 4];
    float4 s4 = *(const float4*)&a_src[lane * 4];
    float4 d4 = *(const float4*)&a_dst[lane * 4];
    float ds = x4.x * s4.x + x4.y * s4.y + x4.z * s4.z + x4.w * s4.w;
    float dd = x4.x * d4.x + x4.y * d4.y + x4.z * d4.z + x4.w * d4.w;
#pragma unroll
    for (int o = 16; o > 0; o >>= 1) {
        ds += __shfl_xor_sync(0xffffffffu, ds, o);
        dd += __shfl_xor_sync(0xffffffffu, dd, o);
    }
    if (lane == 0) {
        g_as1[warp] = ds;
        g_ad1[warp] = dd;
    }
}

// ---------------- segment softmax: normalized attention weight per edge (CSR order) ----------------
__global__ void k_attention() {
    int warp = (blockIdx.x * blockDim.x + threadIdx.x) >> 5;
    int lane = threadIdx.x & 31;
    if (warp >= NN) return;
    int off = g_off[warp];
    int d = g_deg[warp];
    if (d == 0) return;
    float adi = g_ad1[warp];

    float m = -INFINITY;
    for (int k = lane; k < d; k += 32) {
        int s = g_esrc[off + k];
        float v = g_as1[s] + adi;
        v = (v > 0.f) ? v : NEG_SLOPE * v;
        g_wbuf[off + k] = v;
        m = fmaxf(m, v);
    }
#pragma unroll
    for (int o = 16; o > 0; o >>= 1) m = fmaxf(m, __shfl_xor_sync(0xffffffffu, m, o));

    float S = 0.f;
    for (int k = lane; k < d; k += 32) {
        float w = expf(g_wbuf[off + k] - m);
        g_wbuf[off + k] = w;
        S += w;
    }
#pragma unroll
    for (int o = 16; o > 0; o >>= 1) S += __shfl_xor_sync(0xffffffffu, S, o);

    float inv = 1.f / S;
    for (int k = lane; k < d; k += 32) g_wbuf[off + k] *= inv;
}

// ---------------- weighted gather + ELU: out[i] = elu(sum_e a_e * in[src_e]) ----------------
__global__ void k_gather_elu(const float* __restrict__ in, float* __restrict__ out) {
    int warp = (blockIdx.x * blockDim.x + threadIdx.x) >> 5;
    int lane = threadIdx.x & 31;
    if (warp >= NN) return;
    int off = g_off[warp];
    int d = g_deg[warp];
    float4 acc = make_float4(0.f, 0.f, 0.f, 0.f);

    if (d > 0) {
        float a = g_wbuf[off];
        int s = g_esrc[off];
        for (int k = 0; k < d; k++) {
            float an = 0.f;
            int sn = 0;
            if (k + 1 < d) {
                an = g_wbuf[off + k + 1];
                sn = g_esrc[off + k + 1];
            }
            const float4 v = *(const float4*)&in[(size_t)s * HIDD + lane * 4];
            acc.x += a * v.x;
            acc.y += a * v.y;
            acc.z += a * v.z;
            acc.w += a * v.w;
            a = an;
            s = sn;
        }
    }
    // ELU (alpha = 1)
    acc.x = (acc.x > 0.f) ? acc.x : expm1f(acc.x);
    acc.y = (acc.y > 0.f) ? acc.y : expm1f(acc.y);
    acc.z = (acc.z > 0.f) ? acc.z : expm1f(acc.z);
    acc.w = (acc.w > 0.f) ? acc.w : expm1f(acc.w);
    *(float4*)&out[(size_t)warp * HIDD + lane * 4] = acc;
}

// ---------------- launcher ----------------
extern "C" void kernel_launch(void* const* d_in, const int* in_sizes, int n_in,
                              void* d_out, int out_size) {
    const float* x = (const float*)d_in[0];       // [NN, IND]
    const float* W1 = (const float*)d_in[1];      // [IND, HIDD]
    const float* a_src = (const float*)d_in[2];   // [HIDD]
    const float* a_dst = (const float*)d_in[3];   // [HIDD]
    const float* W2 = (const float*)d_in[4];      // [HIDD, OUTD]
    const int* eidx = (const int*)d_in[5];        // [2, NE] int32
    const int* src = eidx;
    const int* dst = eidx + NE;

    float* h2 = (float*)d_out;                       // [NN, OUTD]
    float* h4 = (float*)d_out + (size_t)NN * OUTD;   // [NN, IND]

    float *p_xs1, *p_h1, *p_xs3, *p_h3, *p_W1T, *p_W2T;
    cudaGetSymbolAddress((void**)&p_xs1, g_xs1);
    cudaGetSymbolAddress((void**)&p_h1, g_h1);
    cudaGetSymbolAddress((void**)&p_xs3, g_xs3);
    cudaGetSymbolAddress((void**)&p_h3, g_h3);
    cudaGetSymbolAddress((void**)&p_W1T, g_W1T);
    cudaGetSymbolAddress((void**)&p_W2T, g_W2T);

    const int NBLK = (NN + 1023) / 1024; // 98

    // --- CSR build ---
    k_zero_deg<<<(NN + 255) / 256, 256>>>();
    k_hist<<<(NE + 255) / 256, 256>>>(dst);
    k_scan1<<<NBLK, 1024>>>();
    k_scan2<<<1, 128>>>();
    k_scan3<<<(NN + 255) / 256, 256>>>();
    k_scatter<<<(NE + 255) / 256, 256>>>(src, dst);

    // --- weight transposes ---
    k_transpose_W1<<<(IND * HIDD + 255) / 256, 256>>>(W1);
    k_transpose_W2<<<(HIDD * OUTD + 255) / 256, 256>>>(W2);

    const int GY = (NN + 127) / 128; // 782
    const int WG = (NN * 32 + 255) / 256; // warp-per-node grid

    // --- G1: xs1 = x @ W1  [100k,256]@[256,128] ---
    k_gemm_tc<4, 2, 2, 8><<<dim3(1, GY), 256>>>(x, W1, p_xs1, NN, HIDD, IND);

    // --- per-node logits + softmax weights (shared by both aggregations) ---
    k_logits<<<WG, 256>>>(a_src, a_dst);
    k_attention<<<WG, 256>>>();

    // --- agg1: h1 = elu(A * xs1) ---
    k_gather_elu<<<WG, 256>>>(p_xs1, p_h1);

    // --- G2: h2 = h1 @ W2  [100k,128]@[128,32] ---
    k_gemm_tc<8, 1, 1, 4><<<dim3(1, GY), 256>>>(p_h1, W2, h2, NN, OUTD, HIDD);

    // --- G3: xs3 = h2 @ W2^T  [100k,32]@[32,128] ---
    k_gemm_tc<4, 2, 2, 8><<<dim3(1, GY), 256>>>(h2, p_W2T, p_xs3, NN, HIDD, OUTD);

    // --- agg2: h3 = elu(A * xs3) ---
    k_gather_elu<<<WG, 256>>>(p_xs3, p_h3);

    // --- G4: h4 = h3 @ W1^T  [100k,128]@[128,256] ---
    k_gemm_tc<4, 2, 2, 8><<<dim3(2, GY), 256>>>(p_h3, p_W1T, h4, NN, IND, HIDD);
}

// round 7
// speedup vs baseline: 1.4861x; 1.0724x over previous
#include <cuda_runtime.h>
#include <cuda_bf16.h>
#include <cstdint>
#include <math.h>

#define NN 100000
#define NE 1600000
#define IND 256
#define HIDD 128
#define OUTD 32
#define NEG_SLOPE 0.2f

// ---------------- static scratch (no runtime allocation allowed) ----------------
__device__ float g_xs1[(size_t)NN * HIDD];
__device__ float g_h1[(size_t)NN * HIDD];
__device__ float g_agg2[(size_t)NN * OUTD];
__device__ float g_h3[(size_t)NN * HIDD];
__device__ float g_as1[NN];
__device__ float g_ad1[NN];
__device__ float g_wbuf[NE];
__device__ int   g_deg[NN];
__device__ int   g_off[NN];
__device__ int   g_cur[NN];
__device__ int   g_esrc[NE];
__device__ int   g_stmp[NN];
__device__ int   g_bsum[128];
__device__ int   g_boff[128];
__device__ float g_W1T[HIDD * IND];
__device__ float g_W2T[OUTD * HIDD];

// ---------------- CSR build ----------------
__global__ void k_zero_deg() {
    int i = blockIdx.x * blockDim.x + threadIdx.x;
    if (i < NN) g_deg[i] = 0;
}

__global__ void k_hist(const int* __restrict__ dst) {
    int e = blockIdx.x * blockDim.x + threadIdx.x;
    if (e < NE) atomicAdd(&g_deg[dst[e]], 1);
}

// inclusive block scan (1024-wide chunks)
__global__ void k_scan1() {
    __shared__ int sm[1024];
    int b = blockIdx.x, t = threadIdx.x;
    int i = b * 1024 + t;
    int v = (i < NN) ? g_deg[i] : 0;
    sm[t] = v;
    __syncthreads();
    for (int ofs = 1; ofs < 1024; ofs <<= 1) {
        int x = (t >= ofs) ? sm[t - ofs] : 0;
        __syncthreads();
        sm[t] += x;
        __syncthreads();
    }
    if (i < NN) g_stmp[i] = sm[t];
    if (t == 1023) g_bsum[b] = sm[1023];
}

// parallel scan of the 98 block sums (1 block, 128 threads)
__global__ void k_scan2() {
    __shared__ int sm[128];
    int t = threadIdx.x;
    int v = (t < 98) ? g_bsum[t] : 0;
    sm[t] = v;
    __syncthreads();
    for (int ofs = 1; ofs < 128; ofs <<= 1) {
        int x = (t >= ofs) ? sm[t - ofs] : 0;
        __syncthreads();
        sm[t] += x;
        __syncthreads();
    }
    if (t < 98) g_boff[t] = sm[t] - v; // exclusive
}

__global__ void k_scan3() {
    int i = blockIdx.x * blockDim.x + threadIdx.x;
    if (i < NN) {
        int off = g_stmp[i] - g_deg[i] + g_boff[i >> 10]; // exclusive
        g_off[i] = off;
        g_cur[i] = off;
    }
}

__global__ void k_scatter(const int* __restrict__ src,
                          const int* __restrict__ dst) {
    int e = blockIdx.x * blockDim.x + threadIdx.x;
    if (e < NE) {
        int d = dst[e];
        int pos = atomicAdd(&g_cur[d], 1);
        g_esrc[pos] = src[e];
    }
}

// ---------------- weight transposes ----------------
__global__ void k_transpose_W1(const float* __restrict__ W1) {
    int idx = blockIdx.x * blockDim.x + threadIdx.x; // IND*HIDD
    if (idx < IND * HIDD) {
        int i = idx / HIDD, h = idx % HIDD;
        g_W1T[h * IND + i] = W1[i * HIDD + h];
    }
}

__global__ void k_transpose_W2(const float* __restrict__ W2) {
    int idx = blockIdx.x * blockDim.x + threadIdx.x; // HIDD*OUTD
    if (idx < HIDD * OUTD) {
        int h = idx / OUTD, o = idx % OUTD;
        g_W2T[o * HIDD + h] = W2[h * OUTD + o];
    }
}

// ---------------- tensor-core GEMM (bf16 split, fp32-accurate) ----------------
__device__ __forceinline__ void ldsm_x4(unsigned (&r)[4], unsigned addr) {
    asm volatile("ldmatrix.sync.aligned.m8n8.x4.shared.b16 {%0,%1,%2,%3}, [%4];"
                 : "=r"(r[0]), "=r"(r[1]), "=r"(r[2]), "=r"(r[3]) : "r"(addr));
}
__device__ __forceinline__ void ldsm_x4_t(unsigned (&r)[4], unsigned addr) {
    asm volatile("ldmatrix.sync.aligned.m8n8.x4.trans.shared.b16 {%0,%1,%2,%3}, [%4];"
                 : "=r"(r[0]), "=r"(r[1]), "=r"(r[2]), "=r"(r[3]) : "r"(addr));
}
__device__ __forceinline__ void mma_bf16(float (&c)[4], const unsigned (&a)[4],
                                         const unsigned (&b)[2]) {
    asm volatile(
        "mma.sync.aligned.m16n8k16.row.col.f32.bf16.bf16.f32 "
        "{%0,%1,%2,%3}, {%4,%5,%6,%7}, {%8,%9}, {%0,%1,%2,%3};"
        : "+f"(c[0]), "+f"(c[1]), "+f"(c[2]), "+f"(c[3])
        : "r"(a[0]), "r"(a[1]), "r"(a[2]), "r"(a[3]), "r"(b[0]), "r"(b[1]));
}

__device__ __forceinline__ void split_store(__nv_bfloat16* H, __nv_bfloat16* L,
                                            int idx, float v) {
    __nv_bfloat16 h = __float2bfloat16(v);
    float lo = v - __bfloat162float(h);
    H[idx] = h;
    L[idx] = __float2bfloat16(lo);
}

__device__ __forceinline__ float elu1(float v) {
    return (v > 0.f) ? v : expm1f(v);
}

// C[M,N] = A[M,K] @ B[K,N], fp32 in/out. N % BN == 0, K % 32 == 0. 256 threads.
template <int MWARPS, int NWARPS, int MFRAG, int NFRAG, bool ELU>
__global__ __launch_bounds__(256, 1) void k_gemm_tc(const float* __restrict__ A,
                                                    const float* __restrict__ B,
                                                    float* __restrict__ C,
                                                    int M, int N, int K) {
    constexpr int BM = MWARPS * MFRAG * 16;
    constexpr int BN = NWARPS * NFRAG * 8;
    constexpr int BK = 32;
    constexpr int SA = BK + 8;   // bf16 elems per A smem row
    constexpr int SB = BN + 8;   // bf16 elems per B smem row

    __shared__ alignas(16) __nv_bfloat16 Ah[BM * SA];
    __shared__ alignas(16) __nv_bfloat16 Al[BM * SA];
    __shared__ alignas(16) __nv_bfloat16 Bh[BK * SB];
    __shared__ alignas(16) __nv_bfloat16 Bl[BK * SB];

    const int tid = threadIdx.x;
    const int warp = tid >> 5, lane = tid & 31;
    const int wm = warp % MWARPS, wn = warp / MWARPS;
    const int m0 = blockIdx.y * BM, n0 = blockIdx.x * BN;

    const unsigned sAh = (unsigned)__cvta_generic_to_shared(Ah);
    const unsigned sAl = (unsigned)__cvta_generic_to_shared(Al);
    const unsigned sBh = (unsigned)__cvta_generic_to_shared(Bh);
    const unsigned sBl = (unsigned)__cvta_generic_to_shared(Bl);

    float acc[MFRAG][NFRAG][4];
#pragma unroll
    for (int f = 0; f < MFRAG; f++)
#pragma unroll
        for (int g = 0; g < NFRAG; g++)
#pragma unroll
            for (int i = 0; i < 4; i++) acc[f][g][i] = 0.f;

    for (int k0 = 0; k0 < K; k0 += BK) {
        // --- A tile (BM x BK fp32) -> split bf16 smem ---
#pragma unroll
        for (int i = 0; i < (BM * BK / 4) / 256; i++) {
            int t = tid + i * 256;
            int r = t / (BK / 4);
            int c = (t % (BK / 4)) * 4;
            float4 v = make_float4(0.f, 0.f, 0.f, 0.f);
            if (m0 + r < M) v = *(const float4*)&A[(size_t)(m0 + r) * K + k0 + c];
            int idx = r * SA + c;
            split_store(Ah, Al, idx + 0, v.x);
            split_store(Ah, Al, idx + 1, v.y);
            split_store(Ah, Al, idx + 2, v.z);
            split_store(Ah, Al, idx + 3, v.w);
        }
        // --- B tile (BK x BN fp32) -> split bf16 smem ---
#pragma unroll
        for (int i = 0; i < (BK * BN / 4) / 256; i++) {
            int t = tid + i * 256;
            int r = t / (BN / 4);
            int c = (t % (BN / 4)) * 4;
            float4 v = *(const float4*)&B[(size_t)(k0 + r) * N + n0 + c];
            int idx = r * SB + c;
            split_store(Bh, Bl, idx + 0, v.x);
            split_store(Bh, Bl, idx + 1, v.y);
            split_store(Bh, Bl, idx + 2, v.z);
            split_store(Bh, Bl, idx + 3, v.w);
        }
        __syncthreads();

#pragma unroll
        for (int ks = 0; ks < 2; ks++) {
            unsigned ah[MFRAG][4], al[MFRAG][4];
#pragma unroll
            for (int f = 0; f < MFRAG; f++) {
                int row = wm * (MFRAG * 16) + f * 16 + (lane & 15);
                int col = ks * 16 + (lane >> 4) * 8;
                unsigned off = (unsigned)(row * SA + col) * 2u;
                ldsm_x4(ah[f], sAh + off);
                ldsm_x4(al[f], sAl + off);
            }
            unsigned bhf[NFRAG][2], blf[NFRAG][2];
#pragma unroll
            for (int nb = 0; nb < NFRAG / 2; nb++) {
                int krow = ks * 16 + (lane & 7) + ((lane >> 3) & 1) * 8;
                int col = wn * (NFRAG * 8) + nb * 16 + ((lane >> 4) & 1) * 8;
                unsigned off = (unsigned)(krow * SB + col) * 2u;
                unsigned r4[4];
                ldsm_x4_t(r4, sBh + off);
                bhf[2 * nb][0] = r4[0]; bhf[2 * nb][1] = r4[1];
                bhf[2 * nb + 1][0] = r4[2]; bhf[2 * nb + 1][1] = r4[3];
                ldsm_x4_t(r4, sBl + off);
                blf[2 * nb][0] = r4[0]; blf[2 * nb][1] = r4[1];
                blf[2 * nb + 1][0] = r4[2]; blf[2 * nb + 1][1] = r4[3];
            }
#pragma unroll
            for (int f = 0; f < MFRAG; f++)
#pragma unroll
                for (int g = 0; g < NFRAG; g++) {
                    mma_bf16(acc[f][g], ah[f], bhf[g]);
                    mma_bf16(acc[f][g], al[f], bhf[g]);
                    mma_bf16(acc[f][g], ah[f], blf[g]);
                }
        }
        __syncthreads();
    }

    // --- store C (optional fused ELU) ---
#pragma unroll
    for (int f = 0; f < MFRAG; f++) {
#pragma unroll
        for (int g = 0; g < NFRAG; g++) {
            int r0 = m0 + wm * (MFRAG * 16) + f * 16 + (lane >> 2);
            int cc = n0 + wn * (NFRAG * 8) + g * 8 + (lane & 3) * 2;
            float c0 = acc[f][g][0], c1 = acc[f][g][1];
            float c2 = acc[f][g][2], c3 = acc[f][g][3];
            if (ELU) { c0 = elu1(c0); c1 = elu1(c1); c2 = elu1(c2); c3 = elu1(c3); }
            if (r0 < M) {
                *(float2*)&C[(size_t)r0 * N + cc] = make_float2(c0, c1);
            }
            if (r0 + 8 < M) {
                *(float2*)&C[(size_t)(r0 + 8) * N + cc] = make_float2(c2, c3);
            }
        }
    }
}

// ---------------- per-node attention logits: as1=xs1@a_src, ad1=xs1@a_dst ----------------
__global__ void k_logits(const float* __restrict__ a_src, const float* __restrict__ a_dst) {
    int warp = (blockIdx.x * blockDim.x + threadIdx.x) >> 5;
    int lane = threadIdx.x & 31;
    if (warp >= NN) return;
    float4 x4 = *(const float4*)&g_xs1[(size_t)warp * HIDD + lane * 4];
    float4 s4 = *(const float4*)&a_src[lane * 4];
    float4 d4 = *(const float4*)&a_dst[lane * 4];
    float ds = x4.x * s4.x + x4.y * s4.y + x4.z * s4.z + x4.w * s4.w;
    float dd = x4.x * d4.x + x4.y * d4.y + x4.z * d4.z + x4.w * d4.w;
#pragma unroll
    for (int o = 16; o > 0; o >>= 1) {
        ds += __shfl_xor_sync(0xffffffffu, ds, o);
        dd += __shfl_xor_sync(0xffffffffu, dd, o);
    }
    if (lane == 0) {
        g_as1[warp] = ds;
        g_ad1[warp] = dd;
    }
}

// ---------------- segment softmax: normalized attention weight per edge (CSR order) ----------------
__global__ void k_attention() {
    int warp = (blockIdx.x * blockDim.x + threadIdx.x) >> 5;
    int lane = threadIdx.x & 31;
    if (warp >= NN) return;
    int off = g_off[warp];
    int d = g_deg[warp];
    if (d == 0) return;
    float adi = g_ad1[warp];

    float m = -INFINITY;
    for (int k = lane; k < d; k += 32) {
        int s = g_esrc[off + k];
        float v = g_as1[s] + adi;
        v = (v > 0.f) ? v : NEG_SLOPE * v;
        g_wbuf[off + k] = v;
        m = fmaxf(m, v);
    }
#pragma unroll
    for (int o = 16; o > 0; o >>= 1) m = fmaxf(m, __shfl_xor_sync(0xffffffffu, m, o));

    float S = 0.f;
    for (int k = lane; k < d; k += 32) {
        float w = expf(g_wbuf[off + k] - m);
        g_wbuf[off + k] = w;
        S += w;
    }
#pragma unroll
    for (int o = 16; o > 0; o >>= 1) S += __shfl_xor_sync(0xffffffffu, S, o);

    float inv = 1.f / S;
    for (int k = lane; k < d; k += 32) g_wbuf[off + k] *= inv;
}

// ---------------- weighted gather (+ELU), 128-wide rows ----------------
__global__ void k_gather_elu(const float* __restrict__ in, float* __restrict__ out) {
    int warp = (blockIdx.x * blockDim.x + threadIdx.x) >> 5;
    int lane = threadIdx.x & 31;
    if (warp >= NN) return;
    int off = g_off[warp];
    int d = g_deg[warp];
    float4 acc = make_float4(0.f, 0.f, 0.f, 0.f);

    if (d > 0) {
        float a = g_wbuf[off];
        int s = g_esrc[off];
        for (int k = 0; k < d; k++) {
            float an = 0.f;
            int sn = 0;
            if (k + 1 < d) {
                an = g_wbuf[off + k + 1];
                sn = g_esrc[off + k + 1];
            }
            const float4 v = *(const float4*)&in[(size_t)s * HIDD + lane * 4];
            acc.x += a * v.x;
            acc.y += a * v.y;
            acc.z += a * v.z;
            acc.w += a * v.w;
            a = an;
            s = sn;
        }
    }
    acc.x = elu1(acc.x);
    acc.y = elu1(acc.y);
    acc.z = elu1(acc.z);
    acc.w = elu1(acc.w);
    *(float4*)&out[(size_t)warp * HIDD + lane * 4] = acc;
}

// ---------------- weighted gather, 32-wide rows (no ELU; 4 edges in flight) ----------------
__global__ void k_gather32(const float* __restrict__ in, float* __restrict__ out) {
    int warp = (blockIdx.x * blockDim.x + threadIdx.x) >> 5;
    int lane = threadIdx.x & 31;
    if (warp >= NN) return;
    int off = g_off[warp];
    int d = g_deg[warp];
    int grp = lane >> 3;   // 0..3 : which edge in the 4-wide batch
    int l = lane & 7;      // 0..7 : which float4 of the 32-float row
    float4 acc = make_float4(0.f, 0.f, 0.f, 0.f);

    for (int k = grp; k < d; k += 4) {
        int s = g_esrc[off + k];
        float a = g_wbuf[off + k];
        const float4 v = *(const float4*)&in[(size_t)s * OUTD + l * 4];
        acc.x += a * v.x;
        acc.y += a * v.y;
        acc.z += a * v.z;
        acc.w += a * v.w;
    }
    // reduce across the 4 edge groups (lanes l, l+8, l+16, l+24)
#pragma unroll
    for (int o = 8; o <= 16; o <<= 1) {
        acc.x += __shfl_xor_sync(0xffffffffu, acc.x, o);
        acc.y += __shfl_xor_sync(0xffffffffu, acc.y, o);
        acc.z += __shfl_xor_sync(0xffffffffu, acc.z, o);
        acc.w += __shfl_xor_sync(0xffffffffu, acc.w, o);
    }
    if (lane < 8)
        *(float4*)&out[(size_t)warp * OUTD + l * 4] = acc;
}

// ---------------- launcher ----------------
extern "C" void kernel_launch(void* const* d_in, const int* in_sizes, int n_in,
                              void* d_out, int out_size) {
    const float* x = (const float*)d_in[0];       // [NN, IND]
    const float* W1 = (const float*)d_in[1];      // [IND, HIDD]
    const float* a_src = (const float*)d_in[2];   // [HIDD]
    const float* a_dst = (const float*)d_in[3];   // [HIDD]
    const float* W2 = (const float*)d_in[4];      // [HIDD, OUTD]
    const int* eidx = (const int*)d_in[5];        // [2, NE] int32
    const int* src = eidx;
    const int* dst = eidx + NE;

    float* h2 = (float*)d_out;                       // [NN, OUTD]
    float* h4 = (float*)d_out + (size_t)NN * OUTD;   // [NN, IND]

    float *p_xs1, *p_h1, *p_agg2, *p_h3, *p_W1T, *p_W2T;
    cudaGetSymbolAddress((void**)&p_xs1, g_xs1);
    cudaGetSymbolAddress((void**)&p_h1, g_h1);
    cudaGetSymbolAddress((void**)&p_agg2, g_agg2);
    cudaGetSymbolAddress((void**)&p_h3, g_h3);
    cudaGetSymbolAddress((void**)&p_W1T, g_W1T);
    cudaGetSymbolAddress((void**)&p_W2T, g_W2T);

    const int NBLK = (NN + 1023) / 1024; // 98

    // --- CSR build ---
    k_zero_deg<<<(NN + 255) / 256, 256>>>();
    k_hist<<<(NE + 255) / 256, 256>>>(dst);
    k_scan1<<<NBLK, 1024>>>();
    k_scan2<<<1, 128>>>();
    k_scan3<<<(NN + 255) / 256, 256>>>();
    k_scatter<<<(NE + 255) / 256, 256>>>(src, dst);

    // --- weight transposes ---
    k_transpose_W1<<<(IND * HIDD + 255) / 256, 256>>>(W1);
    k_transpose_W2<<<(HIDD * OUTD + 255) / 256, 256>>>(W2);

    const int GY = (NN + 127) / 128; // 782
    const int WG = (NN * 32 + 255) / 256; // warp-per-node grid

    // --- G1: xs1 = x @ W1  [100k,256]@[256,128] ---
    k_gemm_tc<4, 2, 2, 8, false><<<dim3(1, GY), 256>>>(x, W1, p_xs1, NN, HIDD, IND);

    // --- per-node logits + softmax weights (shared by both aggregations) ---
    k_logits<<<WG, 256>>>(a_src, a_dst);
    k_attention<<<WG, 256>>>();

    // --- agg1: h1 = elu(A * xs1) ---
    k_gather_elu<<<WG, 256>>>(p_xs1, p_h1);

    // --- G2: h2 = h1 @ W2  [100k,128]@[128,32] ---
    k_gemm_tc<8, 1, 1, 4, false><<<dim3(1, GY), 256>>>(p_h1, W2, h2, NN, OUTD, HIDD);

    // --- agg2': A * h2  (32-wide gather; aggregation commutes with @W2^T) ---
    k_gather32<<<WG, 256>>>(h2, p_agg2);

    // --- G3: h3 = elu(agg2' @ W2^T)  [100k,32]@[32,128], fused ELU ---
    k_gemm_tc<4, 2, 2, 8, true><<<dim3(1, GY), 256>>>(p_agg2, p_W2T, p_h3, NN, HIDD, OUTD);

    // --- G4: h4 = h3 @ W1^T  [100k,128]@[128,256] ---
    k_gemm_tc<4, 2, 2, 8, false><<<dim3(2, GY), 256>>>(p_h3, p_W1T, h4, NN, IND, HIDD);
}

// round 8
// speedup vs baseline: 1.7225x; 1.1591x over previous
#include <cuda_runtime.h>
#include <cuda_bf16.h>
#include <cstdint>
#include <math.h>

#define NN 100000
#define NE 1600000
#define IND 256
#define HIDD 128
#define OUTD 32
#define NEG_SLOPE 0.2f

// ---------------- static scratch (no runtime allocation allowed) ----------------
__device__ float g_xs1[(size_t)NN * HIDD];
__device__ float g_h1[(size_t)NN * HIDD];
__device__ float g_agg2[(size_t)NN * OUTD];
__device__ float g_h3[(size_t)NN * HIDD];
__device__ float g_as1[NN];
__device__ float g_ad1[NN];
__device__ float g_invS[NN];
__device__ float g_wbuf[NE];
__device__ int   g_deg[NN];
__device__ int   g_off[NN];
__device__ int   g_cur[NN];
__device__ int   g_esrc[NE];
__device__ int   g_stmp[NN];
__device__ int   g_bsum[128];
__device__ int   g_boff[128];
__device__ float g_W1T[HIDD * IND];
__device__ float g_W2T[OUTD * HIDD];

// ---------------- CSR build ----------------
__global__ void k_zero_deg() {
    int i = blockIdx.x * blockDim.x + threadIdx.x;
    if (i < NN) g_deg[i] = 0;
}

__global__ void k_hist(const int* __restrict__ dst) {
    int e = blockIdx.x * blockDim.x + threadIdx.x;
    if (e < NE) atomicAdd(&g_deg[dst[e]], 1);
}

// inclusive block scan (1024-wide chunks)
__global__ void k_scan1() {
    __shared__ int sm[1024];
    int b = blockIdx.x, t = threadIdx.x;
    int i = b * 1024 + t;
    int v = (i < NN) ? g_deg[i] : 0;
    sm[t] = v;
    __syncthreads();
    for (int ofs = 1; ofs < 1024; ofs <<= 1) {
        int x = (t >= ofs) ? sm[t - ofs] : 0;
        __syncthreads();
        sm[t] += x;
        __syncthreads();
    }
    if (i < NN) g_stmp[i] = sm[t];
    if (t == 1023) g_bsum[b] = sm[1023];
}

// parallel scan of the 98 block sums (1 block, 128 threads)
__global__ void k_scan2() {
    __shared__ int sm[128];
    int t = threadIdx.x;
    int v = (t < 98) ? g_bsum[t] : 0;
    sm[t] = v;
    __syncthreads();
    for (int ofs = 1; ofs < 128; ofs <<= 1) {
        int x = (t >= ofs) ? sm[t - ofs] : 0;
        __syncthreads();
        sm[t] += x;
        __syncthreads();
    }
    if (t < 98) g_boff[t] = sm[t] - v; // exclusive
}

__global__ void k_scan3() {
    int i = blockIdx.x * blockDim.x + threadIdx.x;
    if (i < NN) {
        int off = g_stmp[i] - g_deg[i] + g_boff[i >> 10]; // exclusive
        g_off[i] = off;
        g_cur[i] = off;
    }
}

__global__ void k_scatter(const int* __restrict__ src,
                          const int* __restrict__ dst) {
    int e = blockIdx.x * blockDim.x + threadIdx.x;
    if (e < NE) {
        int d = dst[e];
        int pos = atomicAdd(&g_cur[d], 1);
        g_esrc[pos] = src[e];
    }
}

// ---------------- weight transposes ----------------
__global__ void k_transpose_W1(const float* __restrict__ W1) {
    int idx = blockIdx.x * blockDim.x + threadIdx.x; // IND*HIDD
    if (idx < IND * HIDD) {
        int i = idx / HIDD, h = idx % HIDD;
        g_W1T[h * IND + i] = W1[i * HIDD + h];
    }
}

__global__ void k_transpose_W2(const float* __restrict__ W2) {
    int idx = blockIdx.x * blockDim.x + threadIdx.x; // HIDD*OUTD
    if (idx < HIDD * OUTD) {
        int h = idx / OUTD, o = idx % OUTD;
        g_W2T[o * HIDD + h] = W2[h * OUTD + o];
    }
}

// ---------------- tensor-core GEMM (bf16 split, fp32-accurate) ----------------
__device__ __forceinline__ void ldsm_x4(unsigned (&r)[4], unsigned addr) {
    asm volatile("ldmatrix.sync.aligned.m8n8.x4.shared.b16 {%0,%1,%2,%3}, [%4];"
                 : "=r"(r[0]), "=r"(r[1]), "=r"(r[2]), "=r"(r[3]) : "r"(addr));
}
__device__ __forceinline__ void ldsm_x4_t(unsigned (&r)[4], unsigned addr) {
    asm volatile("ldmatrix.sync.aligned.m8n8.x4.trans.shared.b16 {%0,%1,%2,%3}, [%4];"
                 : "=r"(r[0]), "=r"(r[1]), "=r"(r[2]), "=r"(r[3]) : "r"(addr));
}
__device__ __forceinline__ void mma_bf16(float (&c)[4], const unsigned (&a)[4],
                                         const unsigned (&b)[2]) {
    asm volatile(
        "mma.sync.aligned.m16n8k16.row.col.f32.bf16.bf16.f32 "
        "{%0,%1,%2,%3}, {%4,%5,%6,%7}, {%8,%9}, {%0,%1,%2,%3};"
        : "+f"(c[0]), "+f"(c[1]), "+f"(c[2]), "+f"(c[3])
        : "r"(a[0]), "r"(a[1]), "r"(a[2]), "r"(a[3]), "r"(b[0]), "r"(b[1]));
}

__device__ __forceinline__ void split_store(__nv_bfloat16* H, __nv_bfloat16* L,
                                            int idx, float v) {
    __nv_bfloat16 h = __float2bfloat16(v);
    float lo = v - __bfloat162float(h);
    H[idx] = h;
    L[idx] = __float2bfloat16(lo);
}

__device__ __forceinline__ float elu1(float v) {
    return (v > 0.f) ? v : expm1f(v);
}

// C[M,N] = A[M,K] @ B[K,N], fp32 in/out. N % BN == 0, K % 32 == 0. 256 threads.
// 2-stage register prefetch: next tile's gmem loads overlap current tile's MMAs.
template <int MWARPS, int NWARPS, int MFRAG, int NFRAG, bool ELU>
__global__ __launch_bounds__(256, 1) void k_gemm_tc(const float* __restrict__ A,
                                                    const float* __restrict__ B,
                                                    float* __restrict__ C,
                                                    int M, int N, int K) {
    constexpr int BM = MWARPS * MFRAG * 16;
    constexpr int BN = NWARPS * NFRAG * 8;
    constexpr int BK = 32;
    constexpr int SA = BK + 8;   // bf16 elems per A smem row
    constexpr int SB = BN + 8;   // bf16 elems per B smem row
    constexpr int APF = (BM * BK / 4) / 256;  // float4s per thread (A tile)
    constexpr int BPF = (BK * BN / 4) / 256;  // float4s per thread (B tile)

    __shared__ alignas(16) __nv_bfloat16 Ah[BM * SA];
    __shared__ alignas(16) __nv_bfloat16 Al[BM * SA];
    __shared__ alignas(16) __nv_bfloat16 Bh[BK * SB];
    __shared__ alignas(16) __nv_bfloat16 Bl[BK * SB];

    const int tid = threadIdx.x;
    const int warp = tid >> 5, lane = tid & 31;
    const int wm = warp % MWARPS, wn = warp / MWARPS;
    const int m0 = blockIdx.y * BM, n0 = blockIdx.x * BN;

    const unsigned sAh = (unsigned)__cvta_generic_to_shared(Ah);
    const unsigned sAl = (unsigned)__cvta_generic_to_shared(Al);
    const unsigned sBh = (unsigned)__cvta_generic_to_shared(Bh);
    const unsigned sBl = (unsigned)__cvta_generic_to_shared(Bl);

    float acc[MFRAG][NFRAG][4];
#pragma unroll
    for (int f = 0; f < MFRAG; f++)
#pragma unroll
        for (int g = 0; g < NFRAG; g++)
#pragma unroll
            for (int i = 0; i < 4; i++) acc[f][g][i] = 0.f;

    float4 pa[APF], pb[BPF];

    // prologue: load tile 0 into registers
#pragma unroll
    for (int i = 0; i < APF; i++) {
        int t = tid + i * 256;
        int r = t >> 3;              // BK/4 == 8
        int c = (t & 7) * 4;
        pa[i] = make_float4(0.f, 0.f, 0.f, 0.f);
        if (m0 + r < M) pa[i] = *(const float4*)&A[(size_t)(m0 + r) * K + c];
    }
#pragma unroll
    for (int i = 0; i < BPF; i++) {
        int t = tid + i * 256;
        int r = t / (BN / 4);
        int c = (t % (BN / 4)) * 4;
        pb[i] = *(const float4*)&B[(size_t)r * N + n0 + c];
    }

    for (int k0 = 0; k0 < K; k0 += BK) {
        // convert+store current tile regs -> smem
#pragma unroll
        for (int i = 0; i < APF; i++) {
            int t = tid + i * 256;
            int r = t >> 3;
            int c = (t & 7) * 4;
            int idx = r * SA + c;
            split_store(Ah, Al, idx + 0, pa[i].x);
            split_store(Ah, Al, idx + 1, pa[i].y);
            split_store(Ah, Al, idx + 2, pa[i].z);
            split_store(Ah, Al, idx + 3, pa[i].w);
        }
#pragma unroll
        for (int i = 0; i < BPF; i++) {
            int t = tid + i * 256;
            int r = t / (BN / 4);
            int c = (t % (BN / 4)) * 4;
            int idx = r * SB + c;
            split_store(Bh, Bl, idx + 0, pb[i].x);
            split_store(Bh, Bl, idx + 1, pb[i].y);
            split_store(Bh, Bl, idx + 2, pb[i].z);
            split_store(Bh, Bl, idx + 3, pb[i].w);
        }
        __syncthreads();

        // prefetch next tile gmem -> regs (overlaps MMAs below)
        int k1 = k0 + BK;
        if (k1 < K) {
#pragma unroll
            for (int i = 0; i < APF; i++) {
                int t = tid + i * 256;
                int r = t >> 3;
                int c = (t & 7) * 4;
                pa[i] = make_float4(0.f, 0.f, 0.f, 0.f);
                if (m0 + r < M) pa[i] = *(const float4*)&A[(size_t)(m0 + r) * K + k1 + c];
            }
#pragma unroll
            for (int i = 0; i < BPF; i++) {
                int t = tid + i * 256;
                int r = t / (BN / 4);
                int c = (t % (BN / 4)) * 4;
                pb[i] = *(const float4*)&B[(size_t)(k1 + r) * N + n0 + c];
            }
        }

#pragma unroll
        for (int ks = 0; ks < 2; ks++) {
            unsigned ah[MFRAG][4], al[MFRAG][4];
#pragma unroll
            for (int f = 0; f < MFRAG; f++) {
                int row = wm * (MFRAG * 16) + f * 16 + (lane & 15);
                int col = ks * 16 + (lane >> 4) * 8;
                unsigned off = (unsigned)(row * SA + col) * 2u;
                ldsm_x4(ah[f], sAh + off);
                ldsm_x4(al[f], sAl + off);
            }
            unsigned bhf[NFRAG][2], blf[NFRAG][2];
#pragma unroll
            for (int nb = 0; nb < NFRAG / 2; nb++) {
                int krow = ks * 16 + (lane & 7) + ((lane >> 3) & 1) * 8;
                int col = wn * (NFRAG * 8) + nb * 16 + ((lane >> 4) & 1) * 8;
                unsigned off = (unsigned)(krow * SB + col) * 2u;
                unsigned r4[4];
                ldsm_x4_t(r4, sBh + off);
                bhf[2 * nb][0] = r4[0]; bhf[2 * nb][1] = r4[1];
                bhf[2 * nb + 1][0] = r4[2]; bhf[2 * nb + 1][1] = r4[3];
                ldsm_x4_t(r4, sBl + off);
                blf[2 * nb][0] = r4[0]; blf[2 * nb][1] = r4[1];
                blf[2 * nb + 1][0] = r4[2]; blf[2 * nb + 1][1] = r4[3];
            }
#pragma unroll
            for (int f = 0; f < MFRAG; f++)
#pragma unroll
                for (int g = 0; g < NFRAG; g++) {
                    mma_bf16(acc[f][g], ah[f], bhf[g]);
                    mma_bf16(acc[f][g], al[f], bhf[g]);
                    mma_bf16(acc[f][g], ah[f], blf[g]);
                }
        }
        __syncthreads();
    }

    // --- store C (optional fused ELU) ---
#pragma unroll
    for (int f = 0; f < MFRAG; f++) {
#pragma unroll
        for (int g = 0; g < NFRAG; g++) {
            int r0 = m0 + wm * (MFRAG * 16) + f * 16 + (lane >> 2);
            int cc = n0 + wn * (NFRAG * 8) + g * 8 + (lane & 3) * 2;
            float c0 = acc[f][g][0], c1 = acc[f][g][1];
            float c2 = acc[f][g][2], c3 = acc[f][g][3];
            if (ELU) { c0 = elu1(c0); c1 = elu1(c1); c2 = elu1(c2); c3 = elu1(c3); }
            if (r0 < M) {
                *(float2*)&C[(size_t)r0 * N + cc] = make_float2(c0, c1);
            }
            if (r0 + 8 < M) {
                *(float2*)&C[(size_t)(r0 + 8) * N + cc] = make_float2(c2, c3);
            }
        }
    }
}

// ---------------- per-node attention logits: as1=xs1@a_src, ad1=xs1@a_dst ----------------
__global__ void k_logits(const float* __restrict__ a_src, const float* __restrict__ a_dst) {
    int warp = (blockIdx.x * blockDim.x + threadIdx.x) >> 5;
    int lane = threadIdx.x & 31;
    if (warp >= NN) return;
    float4 x4 = *(const float4*)&g_xs1[(size_t)warp * HIDD + lane * 4];
    float4 s4 = *(const float4*)&a_src[lane * 4];
    float4 d4 = *(const float4*)&a_dst[lane * 4];
    float ds = x4.x * s4.x + x4.y * s4.y + x4.z * s4.z + x4.w * s4.w;
    float dd = x4.x * d4.x + x4.y * d4.y + x4.z * d4.z + x4.w * d4.w;
#pragma unroll
    for (int o = 16; o > 0; o >>= 1) {
        ds += __shfl_xor_sync(0xffffffffu, ds, o);
        dd += __shfl_xor_sync(0xffffffffu, dd, o);
    }
    if (lane == 0) {
        g_as1[warp] = ds;
        g_ad1[warp] = dd;
    }
}

// ---------------- single-pass edge weights: w=exp(leaky(...)), invS per node ----------------
// softmax is shift-invariant; logits are O(few), so no max-subtraction needed.
// Normalization (1/S) is deferred into the gather epilogues.
__global__ void k_weights() {
    int warp = (blockIdx.x * blockDim.x + threadIdx.x) >> 5;
    int lane = threadIdx.x & 31;
    if (warp >= NN) return;
    int off = g_off[warp];
    int d = g_deg[warp];
    float adi = (d > 0) ? g_ad1[warp] : 0.f;

    float S = 0.f;
    for (int k = lane; k < d; k += 32) {
        int s = g_esrc[off + k];
        float v = g_as1[s] + adi;
        v = (v > 0.f) ? v : NEG_SLOPE * v;
        float w = expf(v);
        g_wbuf[off + k] = w;
        S += w;
    }
#pragma unroll
    for (int o = 16; o > 0; o >>= 1) S += __shfl_xor_sync(0xffffffffu, S, o);
    if (lane == 0) g_invS[warp] = (d > 0) ? 1.f / S : 0.f;
}

// ---------------- weighted gather (+ELU), 128-wide rows ----------------
__global__ void k_gather_elu(const float* __restrict__ in, float* __restrict__ out) {
    int warp = (blockIdx.x * blockDim.x + threadIdx.x) >> 5;
    int lane = threadIdx.x & 31;
    if (warp >= NN) return;
    int off = g_off[warp];
    int d = g_deg[warp];
    float4 acc = make_float4(0.f, 0.f, 0.f, 0.f);

    if (d > 0) {
        float a = g_wbuf[off];
        int s = g_esrc[off];
        for (int k = 0; k < d; k++) {
            float an = 0.f;
            int sn = 0;
            if (k + 1 < d) {
                an = g_wbuf[off + k + 1];
                sn = g_esrc[off + k + 1];
            }
            const float4 v = *(const float4*)&in[(size_t)s * HIDD + lane * 4];
            acc.x += a * v.x;
            acc.y += a * v.y;
            acc.z += a * v.z;
            acc.w += a * v.w;
            a = an;
            s = sn;
        }
    }
    float inv = g_invS[warp];
    acc.x = elu1(acc.x * inv);
    acc.y = elu1(acc.y * inv);
    acc.z = elu1(acc.z * inv);
    acc.w = elu1(acc.w * inv);
    *(float4*)&out[(size_t)warp * HIDD + lane * 4] = acc;
}

// ---------------- weighted gather, 32-wide rows (no ELU; 4 edges in flight) ----------------
__global__ void k_gather32(const float* __restrict__ in, float* __restrict__ out) {
    int warp = (blockIdx.x * blockDim.x + threadIdx.x) >> 5;
    int lane = threadIdx.x & 31;
    if (warp >= NN) return;
    int off = g_off[warp];
    int d = g_deg[warp];
    int grp = lane >> 3;   // 0..3 : which edge in the 4-wide batch
    int l = lane & 7;      // 0..7 : which float4 of the 32-float row
    float4 acc = make_float4(0.f, 0.f, 0.f, 0.f);

    for (int k = grp; k < d; k += 4) {
        int s = g_esrc[off + k];
        float a = g_wbuf[off + k];
        const float4 v = *(const float4*)&in[(size_t)s * OUTD + l * 4];
        acc.x += a * v.x;
        acc.y += a * v.y;
        acc.z += a * v.z;
        acc.w += a * v.w;
    }
    // reduce across the 4 edge groups (lanes l, l+8, l+16, l+24)
#pragma unroll
    for (int o = 8; o <= 16; o <<= 1) {
        acc.x += __shfl_xor_sync(0xffffffffu, acc.x, o);
        acc.y += __shfl_xor_sync(0xffffffffu, acc.y, o);
        acc.z += __shfl_xor_sync(0xffffffffu, acc.z, o);
        acc.w += __shfl_xor_sync(0xffffffffu, acc.w, o);
    }
    if (lane < 8) {
        float inv = g_invS[warp];
        acc.x *= inv; acc.y *= inv; acc.z *= inv; acc.w *= inv;
        *(float4*)&out[(size_t)warp * OUTD + l * 4] = acc;
    }
}

// ---------------- launcher ----------------
extern "C" void kernel_launch(void* const* d_in, const int* in_sizes, int n_in,
                              void* d_out, int out_size) {
    const float* x = (const float*)d_in[0];       // [NN, IND]
    const float* W1 = (const float*)d_in[1];      // [IND, HIDD]
    const float* a_src = (const float*)d_in[2];   // [HIDD]
    const float* a_dst = (const float*)d_in[3];   // [HIDD]
    const float* W2 = (const float*)d_in[4];      // [HIDD, OUTD]
    const int* eidx = (const int*)d_in[5];        // [2, NE] int32
    const int* src = eidx;
    const int* dst = eidx + NE;

    float* h2 = (float*)d_out;                       // [NN, OUTD]
    float* h4 = (float*)d_out + (size_t)NN * OUTD;   // [NN, IND]

    float *p_xs1, *p_h1, *p_agg2, *p_h3, *p_W1T, *p_W2T;
    cudaGetSymbolAddress((void**)&p_xs1, g_xs1);
    cudaGetSymbolAddress((void**)&p_h1, g_h1);
    cudaGetSymbolAddress((void**)&p_agg2, g_agg2);
    cudaGetSymbolAddress((void**)&p_h3, g_h3);
    cudaGetSymbolAddress((void**)&p_W1T, g_W1T);
    cudaGetSymbolAddress((void**)&p_W2T, g_W2T);

    const int NBLK = (NN + 1023) / 1024; // 98

    // --- CSR build ---
    k_zero_deg<<<(NN + 255) / 256, 256>>>();
    k_hist<<<(NE + 255) / 256, 256>>>(dst);
    k_scan1<<<NBLK, 1024>>>();
    k_scan2<<<1, 128>>>();
    k_scan3<<<(NN + 255) / 256, 256>>>();
    k_scatter<<<(NE + 255) / 256, 256>>>(src, dst);

    // --- weight transposes ---
    k_transpose_W1<<<(IND * HIDD + 255) / 256, 256>>>(W1);
    k_transpose_W2<<<(HIDD * OUTD + 255) / 256, 256>>>(W2);

    const int GY = (NN + 127) / 128; // 782
    const int WG = (NN * 32 + 255) / 256; // warp-per-node grid

    // --- G1: xs1 = x @ W1  [100k,256]@[256,128] ---
    k_gemm_tc<4, 2, 2, 8, false><<<dim3(1, GY), 256>>>(x, W1, p_xs1, NN, HIDD, IND);

    // --- per-node logits + single-pass edge weights (shared by both aggregations) ---
    k_logits<<<WG, 256>>>(a_src, a_dst);
    k_weights<<<WG, 256>>>();

    // --- agg1: h1 = elu(A * xs1) ---
    k_gather_elu<<<WG, 256>>>(p_xs1, p_h1);

    // --- G2: h2 = h1 @ W2  [100k,128]@[128,32] ---
    k_gemm_tc<8, 1, 1, 4, false><<<dim3(1, GY), 256>>>(p_h1, W2, h2, NN, OUTD, HIDD);

    // --- agg2': A * h2  (32-wide gather; aggregation commutes with @W2^T) ---
    k_gather32<<<WG, 256>>>(h2, p_agg2);

    // --- G3: h3 = elu(agg2' @ W2^T)  [100k,32]@[32,128], fused ELU ---
    k_gemm_tc<4, 2, 2, 8, true><<<dim3(1, GY), 256>>>(p_agg2, p_W2T, p_h3, NN, HIDD, OUTD);

    // --- G4: h4 = h3 @ W1^T  [100k,128]@[128,256] ---
    k_gemm_tc<4, 2, 2, 8, false><<<dim3(2, GY), 256>>>(p_h3, p_W1T, h4, NN, IND, HIDD);
}

// round 12
// speedup vs baseline: 1.7813x; 1.0341x over previous
#include <cuda_runtime.h>
#include <cuda_bf16.h>
#include <cstdint>
#include <math.h>

#define NN 100000
#define NE 1600000
#define IND 256
#define HIDD 128
#define OUTD 32
#define NEG_SLOPE 0.2f

// ---------------- static scratch (no runtime allocation allowed) ----------------
__device__ float g_xs1[(size_t)NN * HIDD];
__device__ float g_h1[(size_t)NN * HIDD];
__device__ float g_agg2[(size_t)NN * OUTD];
__device__ float g_h3[(size_t)NN * HIDD];
__device__ float g_as1[NN];
__device__ float g_ad1[NN];
__device__ float g_invS[NN];
__device__ float g_wbuf[NE];
__device__ int   g_deg[NN];
__device__ int   g_off[NN];
__device__ int   g_cur[NN];
__device__ int   g_esrc[NE];
__device__ int   g_stmp[NN];
__device__ int   g_bsum[128];
__device__ int   g_boff[128];
__device__ float g_W1T[HIDD * IND];
__device__ float g_W2T[OUTD * HIDD];

// ---------------- CSR build ----------------
__global__ void k_zero_deg() {
    int i = blockIdx.x * blockDim.x + threadIdx.x;
    if (i < NN) g_deg[i] = 0;
}

__global__ void k_hist(const int* __restrict__ dst) {
    int e = blockIdx.x * blockDim.x + threadIdx.x;
    if (e < NE) atomicAdd(&g_deg[dst[e]], 1);
}

// inclusive block scan (1024-wide chunks)
__global__ void k_scan1() {
    __shared__ int sm[1024];
    int b = blockIdx.x, t = threadIdx.x;
    int i = b * 1024 + t;
    int v = (i < NN) ? g_deg[i] : 0;
    sm[t] = v;
    __syncthreads();
    for (int ofs = 1; ofs < 1024; ofs <<= 1) {
        int x = (t >= ofs) ? sm[t - ofs] : 0;
        __syncthreads();
        sm[t] += x;
        __syncthreads();
    }
    if (i < NN) g_stmp[i] = sm[t];
    if (t == 1023) g_bsum[b] = sm[1023];
}

// parallel scan of the 98 block sums (1 block, 128 threads)
__global__ void k_scan2() {
    __shared__ int sm[128];
    int t = threadIdx.x;
    int v = (t < 98) ? g_bsum[t] : 0;
    sm[t] = v;
    __syncthreads();
    for (int ofs = 1; ofs < 128; ofs <<= 1) {
        int x = (t >= ofs) ? sm[t - ofs] : 0;
        __syncthreads();
        sm[t] += x;
        __syncthreads();
    }
    if (t < 98) g_boff[t] = sm[t] - v; // exclusive
}

__global__ void k_scan3() {
    int i = blockIdx.x * blockDim.x + threadIdx.x;
    if (i < NN) {
        int off = g_stmp[i] - g_deg[i] + g_boff[i >> 10]; // exclusive
        g_off[i] = off;
        g_cur[i] = off;
    }
}

__global__ void k_scatter(const int* __restrict__ src,
                          const int* __restrict__ dst) {
    int e = blockIdx.x * blockDim.x + threadIdx.x;
    if (e < NE) {
        int d = dst[e];
        int pos = atomicAdd(&g_cur[d], 1);
        g_esrc[pos] = src[e];
    }
}

// ---------------- weight transposes ----------------
__global__ void k_transpose_W1(const float* __restrict__ W1) {
    int idx = blockIdx.x * blockDim.x + threadIdx.x; // IND*HIDD
    if (idx < IND * HIDD) {
        int i = idx / HIDD, h = idx % HIDD;
        g_W1T[h * IND + i] = W1[i * HIDD + h];
    }
}

__global__ void k_transpose_W2(const float* __restrict__ W2) {
    int idx = blockIdx.x * blockDim.x + threadIdx.x; // HIDD*OUTD
    if (idx < HIDD * OUTD) {
        int h = idx / OUTD, o = idx % OUTD;
        g_W2T[o * HIDD + h] = W2[h * OUTD + o];
    }
}

// ---------------- tensor-core GEMM (bf16 split, fp32-accurate) ----------------
__device__ __forceinline__ void ldsm_x4(unsigned (&r)[4], unsigned addr) {
    asm volatile("ldmatrix.sync.aligned.m8n8.x4.shared.b16 {%0,%1,%2,%3}, [%4];"
                 : "=r"(r[0]), "=r"(r[1]), "=r"(r[2]), "=r"(r[3]) : "r"(addr));
}
__device__ __forceinline__ void ldsm_x4_t(unsigned (&r)[4], unsigned addr) {
    asm volatile("ldmatrix.sync.aligned.m8n8.x4.trans.shared.b16 {%0,%1,%2,%3}, [%4];"
                 : "=r"(r[0]), "=r"(r[1]), "=r"(r[2]), "=r"(r[3]) : "r"(addr));
}
__device__ __forceinline__ void mma_bf16(float (&c)[4], const unsigned (&a)[4],
                                         const unsigned (&b)[2]) {
    asm volatile(
        "mma.sync.aligned.m16n8k16.row.col.f32.bf16.bf16.f32 "
        "{%0,%1,%2,%3}, {%4,%5,%6,%7}, {%8,%9}, {%0,%1,%2,%3};"
        : "+f"(c[0]), "+f"(c[1]), "+f"(c[2]), "+f"(c[3])
        : "r"(a[0]), "r"(a[1]), "r"(a[2]), "r"(a[3]), "r"(b[0]), "r"(b[1]));
}

__device__ __forceinline__ void split_store(__nv_bfloat16* H, __nv_bfloat16* L,
                                            int idx, float v) {
    __nv_bfloat16 h = __float2bfloat16(v);
    float lo = v - __bfloat162float(h);
    H[idx] = h;
    L[idx] = __float2bfloat16(lo);
}

__device__ __forceinline__ float elu1(float v) {
    return (v > 0.f) ? v : expm1f(v);
}

// C[M,N] = A[M,K] @ B[K,N], fp32 in/out. N % BN == 0, K % 32 == 0. 256 threads.
// 2-stage register prefetch: next tile's gmem loads overlap current tile's MMAs.
template <int MWARPS, int NWARPS, int MFRAG, int NFRAG, bool ELU>
__global__ __launch_bounds__(256, 1) void k_gemm_tc(const float* __restrict__ A,
                                                    const float* __restrict__ B,
                                                    float* __restrict__ C,
                                                    int M, int N, int K) {
    constexpr int BM = MWARPS * MFRAG * 16;
    constexpr int BN = NWARPS * NFRAG * 8;
    constexpr int BK = 32;
    constexpr int SA = BK + 8;   // bf16 elems per A smem row
    constexpr int SB = BN + 8;   // bf16 elems per B smem row
    constexpr int APF = (BM * BK / 4) / 256;  // float4s per thread (A tile)
    constexpr int BPF = (BK * BN / 4) / 256;  // float4s per thread (B tile)

    __shared__ alignas(16) __nv_bfloat16 Ah[BM * SA];
    __shared__ alignas(16) __nv_bfloat16 Al[BM * SA];
    __shared__ alignas(16) __nv_bfloat16 Bh[BK * SB];
    __shared__ alignas(16) __nv_bfloat16 Bl[BK * SB];

    const int tid = threadIdx.x;
    const int warp = tid >> 5, lane = tid & 31;
    const int wm = warp % MWARPS, wn = warp / MWARPS;
    const int m0 = blockIdx.y * BM, n0 = blockIdx.x * BN;

    const unsigned sAh = (unsigned)__cvta_generic_to_shared(Ah);
    const unsigned sAl = (unsigned)__cvta_generic_to_shared(Al);
    const unsigned sBh = (unsigned)__cvta_generic_to_shared(Bh);
    const unsigned sBl = (unsigned)__cvta_generic_to_shared(Bl);

    float acc[MFRAG][NFRAG][4];
#pragma unroll
    for (int f = 0; f < MFRAG; f++)
#pragma unroll
        for (int g = 0; g < NFRAG; g++)
#pragma unroll
            for (int i = 0; i < 4; i++) acc[f][g][i] = 0.f;

    float4 pa[APF], pb[BPF];

    // prologue: load tile 0 into registers
#pragma unroll
    for (int i = 0; i < APF; i++) {
        int t = tid + i * 256;
        int r = t >> 3;              // BK/4 == 8
        int c = (t & 7) * 4;
        pa[i] = make_float4(0.f, 0.f, 0.f, 0.f);
        if (m0 + r < M) pa[i] = *(const float4*)&A[(size_t)(m0 + r) * K + c];
    }
#pragma unroll
    for (int i = 0; i < BPF; i++) {
        int t = tid + i * 256;
        int r = t / (BN / 4);
        int c = (t % (BN / 4)) * 4;
        pb[i] = *(const float4*)&B[(size_t)r * N + n0 + c];
    }

    for (int k0 = 0; k0 < K; k0 += BK) {
        // convert+store current tile regs -> smem
#pragma unroll
        for (int i = 0; i < APF; i++) {
            int t = tid + i * 256;
            int r = t >> 3;
            int c = (t & 7) * 4;
            int idx = r * SA + c;
            split_store(Ah, Al, idx + 0, pa[i].x);
            split_store(Ah, Al, idx + 1, pa[i].y);
            split_store(Ah, Al, idx + 2, pa[i].z);
            split_store(Ah, Al, idx + 3, pa[i].w);
        }
#pragma unroll
        for (int i = 0; i < BPF; i++) {
            int t = tid + i * 256;
            int r = t / (BN / 4);
            int c = (t % (BN / 4)) * 4;
            int idx = r * SB + c;
            split_store(Bh, Bl, idx + 0, pb[i].x);
            split_store(Bh, Bl, idx + 1, pb[i].y);
            split_store(Bh, Bl, idx + 2, pb[i].z);
            split_store(Bh, Bl, idx + 3, pb[i].w);
        }
        __syncthreads();

        // prefetch next tile gmem -> regs (overlaps MMAs below)
        int k1 = k0 + BK;
        if (k1 < K) {
#pragma unroll
            for (int i = 0; i < APF; i++) {
                int t = tid + i * 256;
                int r = t >> 3;
                int c = (t & 7) * 4;
                pa[i] = make_float4(0.f, 0.f, 0.f, 0.f);
                if (m0 + r < M) pa[i] = *(const float4*)&A[(size_t)(m0 + r) * K + k1 + c];
            }
#pragma unroll
            for (int i = 0; i < BPF; i++) {
                int t = tid + i * 256;
                int r = t / (BN / 4);
                int c = (t % (BN / 4)) * 4;
                pb[i] = *(const float4*)&B[(size_t)(k1 + r) * N + n0 + c];
            }
        }

#pragma unroll
        for (int ks = 0; ks < 2; ks++) {
            unsigned ah[MFRAG][4], al[MFRAG][4];
#pragma unroll
            for (int f = 0; f < MFRAG; f++) {
                int row = wm * (MFRAG * 16) + f * 16 + (lane & 15);
                int col = ks * 16 + (lane >> 4) * 8;
                unsigned off = (unsigned)(row * SA + col) * 2u;
                ldsm_x4(ah[f], sAh + off);
                ldsm_x4(al[f], sAl + off);
            }
            unsigned bhf[NFRAG][2], blf[NFRAG][2];
#pragma unroll
            for (int nb = 0; nb < NFRAG / 2; nb++) {
                int krow = ks * 16 + (lane & 7) + ((lane >> 3) & 1) * 8;
                int col = wn * (NFRAG * 8) + nb * 16 + ((lane >> 4) & 1) * 8;
                unsigned off = (unsigned)(krow * SB + col) * 2u;
                unsigned r4[4];
                ldsm_x4_t(r4, sBh + off);
                bhf[2 * nb][0] = r4[0]; bhf[2 * nb][1] = r4[1];
                bhf[2 * nb + 1][0] = r4[2]; bhf[2 * nb + 1][1] = r4[3];
                ldsm_x4_t(r4, sBl + off);
                blf[2 * nb][0] = r4[0]; blf[2 * nb][1] = r4[1];
                blf[2 * nb + 1][0] = r4[2]; blf[2 * nb + 1][1] = r4[3];
            }
#pragma unroll
            for (int f = 0; f < MFRAG; f++)
#pragma unroll
                for (int g = 0; g < NFRAG; g++) {
                    mma_bf16(acc[f][g], ah[f], bhf[g]);
                    mma_bf16(acc[f][g], al[f], bhf[g]);
                    mma_bf16(acc[f][g], ah[f], blf[g]);
                }
        }
        __syncthreads();
    }

    // --- store C (optional fused ELU) ---
#pragma unroll
    for (int f = 0; f < MFRAG; f++) {
#pragma unroll
        for (int g = 0; g < NFRAG; g++) {
            int r0 = m0 + wm * (MFRAG * 16) + f * 16 + (lane >> 2);
            int cc = n0 + wn * (NFRAG * 8) + g * 8 + (lane & 3) * 2;
            float c0 = acc[f][g][0], c1 = acc[f][g][1];
            float c2 = acc[f][g][2], c3 = acc[f][g][3];
            if (ELU) { c0 = elu1(c0); c1 = elu1(c1); c2 = elu1(c2); c3 = elu1(c3); }
            if (r0 < M) {
                *(float2*)&C[(size_t)r0 * N + cc] = make_float2(c0, c1);
            }
            if (r0 + 8 < M) {
                *(float2*)&C[(size_t)(r0 + 8) * N + cc] = make_float2(c2, c3);
            }
        }
    }
}

// ---------------- per-node attention logits: as1=xs1@a_src, ad1=xs1@a_dst ----------------
__global__ void k_logits(const float* __restrict__ a_src, const float* __restrict__ a_dst) {
    int warp = (blockIdx.x * blockDim.x + threadIdx.x) >> 5;
    int lane = threadIdx.x & 31;
    if (warp >= NN) return;
    float4 x4 = *(const float4*)&g_xs1[(size_t)warp * HIDD + lane * 4];
    float4 s4 = *(const float4*)&a_src[lane * 4];
    float4 d4 = *(const float4*)&a_dst[lane * 4];
    float ds = x4.x * s4.x + x4.y * s4.y + x4.z * s4.z + x4.w * s4.w;
    float dd = x4.x * d4.x + x4.y * d4.y + x4.z * d4.z + x4.w * d4.w;
#pragma unroll
    for (int o = 16; o > 0; o >>= 1) {
        ds += __shfl_xor_sync(0xffffffffu, ds, o);
        dd += __shfl_xor_sync(0xffffffffu, dd, o);
    }
    if (lane == 0) {
        g_as1[warp] = ds;
        g_ad1[warp] = dd;
    }
}

// ---------------- single-pass edge weights: w=exp(leaky(...)), invS per node ----------------
// softmax is shift-invariant; logits are O(few), so no max-subtraction needed.
// Normalization (1/S) is deferred into the gather epilogues.
__global__ void k_weights() {
    int warp = (blockIdx.x * blockDim.x + threadIdx.x) >> 5;
    int lane = threadIdx.x & 31;
    if (warp >= NN) return;
    int off = g_off[warp];
    int d = g_deg[warp];
    float adi = (d > 0) ? g_ad1[warp] : 0.f;

    float S = 0.f;
    for (int k = lane; k < d; k += 32) {
        int s = g_esrc[off + k];
        float v = g_as1[s] + adi;
        v = (v > 0.f) ? v : NEG_SLOPE * v;
        float w = expf(v);
        g_wbuf[off + k] = w;
        S += w;
    }
#pragma unroll
    for (int o = 16; o > 0; o >>= 1) S += __shfl_xor_sync(0xffffffffu, S, o);
    if (lane == 0) g_invS[warp] = (d > 0) ? 1.f / S : 0.f;
}

// ---------------- weighted gather (+ELU), 128-wide rows, 2 edges in flight ----------------
__global__ void k_gather_elu(const float* __restrict__ in, float* __restrict__ out) {
    int warp = (blockIdx.x * blockDim.x + threadIdx.x) >> 5;
    int lane = threadIdx.x & 31;
    if (warp >= NN) return;
    int off = g_off[warp];
    int d = g_deg[warp];
    float4 acc = make_float4(0.f, 0.f, 0.f, 0.f);

    int k = 0;
    for (; k + 2 <= d; k += 2) {
        int s0 = g_esrc[off + k];
        int s1 = g_esrc[off + k + 1];
        float a0 = g_wbuf[off + k];
        float a1 = g_wbuf[off + k + 1];
        const float4 v0 = *(const float4*)&in[(size_t)s0 * HIDD + lane * 4];
        const float4 v1 = *(const float4*)&in[(size_t)s1 * HIDD + lane * 4];
        acc.x += a0 * v0.x + a1 * v1.x;
        acc.y += a0 * v0.y + a1 * v1.y;
        acc.z += a0 * v0.z + a1 * v1.z;
        acc.w += a0 * v0.w + a1 * v1.w;
    }
    if (k < d) {
        int s0 = g_esrc[off + k];
        float a0 = g_wbuf[off + k];
        const float4 v0 = *(const float4*)&in[(size_t)s0 * HIDD + lane * 4];
        acc.x += a0 * v0.x;
        acc.y += a0 * v0.y;
        acc.z += a0 * v0.z;
        acc.w += a0 * v0.w;
    }
    float inv = g_invS[warp];
    acc.x = elu1(acc.x * inv);
    acc.y = elu1(acc.y * inv);
    acc.z = elu1(acc.z * inv);
    acc.w = elu1(acc.w * inv);
    *(float4*)&out[(size_t)warp * HIDD + lane * 4] = acc;
}

// ---------------- weighted gather, 32-wide rows (no ELU; 4 edges in flight) ----------------
__global__ void k_gather32(const float* __restrict__ in, float* __restrict__ out) {
    int warp = (blockIdx.x * blockDim.x + threadIdx.x) >> 5;
    int lane = threadIdx.x & 31;
    if (warp >= NN) return;
    int off = g_off[warp];
    int d = g_deg[warp];
    int grp = lane >> 3;   // 0..3 : which edge in the 4-wide batch
    int l = lane & 7;      // 0..7 : which float4 of the 32-float row
    float4 acc = make_float4(0.f, 0.f, 0.f, 0.f);

    for (int k = grp; k < d; k += 4) {
        int s = g_esrc[off + k];
        float a = g_wbuf[off + k];
        const float4 v = *(const float4*)&in[(size_t)s * OUTD + l * 4];
        acc.x += a * v.x;
        acc.y += a * v.y;
        acc.z += a * v.z;
        acc.w += a * v.w;
    }
    // reduce across the 4 edge groups (lanes l, l+8, l+16, l+24)
#pragma unroll
    for (int o = 8; o <= 16; o <<= 1) {
        acc.x += __shfl_xor_sync(0xffffffffu, acc.x, o);
        acc.y += __shfl_xor_sync(0xffffffffu, acc.y, o);
        acc.z += __shfl_xor_sync(0xffffffffu, acc.z, o);
        acc.w += __shfl_xor_sync(0xffffffffu, acc.w, o);
    }
    if (lane < 8) {
        float inv = g_invS[warp];
        acc.x *= inv; acc.y *= inv; acc.z *= inv; acc.w *= inv;
        *(float4*)&out[(size_t)warp * OUTD + l * 4] = acc;
    }
}

// ---------------- launcher ----------------
extern "C" void kernel_launch(void* const* d_in, const int* in_sizes, int n_in,
                              void* d_out, int out_size) {
    const float* x = (const float*)d_in[0];       // [NN, IND]
    const float* W1 = (const float*)d_in[1];      // [IND, HIDD]
    const float* a_src = (const float*)d_in[2];   // [HIDD]
    const float* a_dst = (const float*)d_in[3];   // [HIDD]
    const float* W2 = (const float*)d_in[4];      // [HIDD, OUTD]
    const int* eidx = (const int*)d_in[5];        // [2, NE] int32
    const int* src = eidx;
    const int* dst = eidx + NE;

    float* h2 = (float*)d_out;                       // [NN, OUTD]
    float* h4 = (float*)d_out + (size_t)NN * OUTD;   // [NN, IND]

    float *p_xs1, *p_h1, *p_agg2, *p_h3, *p_W1T, *p_W2T;
    cudaGetSymbolAddress((void**)&p_xs1, g_xs1);
    cudaGetSymbolAddress((void**)&p_h1, g_h1);
    cudaGetSymbolAddress((void**)&p_agg2, g_agg2);
    cudaGetSymbolAddress((void**)&p_h3, g_h3);
    cudaGetSymbolAddress((void**)&p_W1T, g_W1T);
    cudaGetSymbolAddress((void**)&p_W2T, g_W2T);

    // side stream + fork/join events, created once on the (uncaptured)
    // correctness call; only launches/record/wait are captured.
    static cudaStream_t s2 = nullptr;
    static cudaEvent_t evFork = nullptr, evJoin = nullptr;
    if (s2 == nullptr) {
        cudaStreamCreateWithFlags(&s2, cudaStreamNonBlocking);
        cudaEventCreateWithFlags(&evFork, cudaEventDisableTiming);
        cudaEventCreateWithFlags(&evJoin, cudaEventDisableTiming);
    }

    const int NBLK = (NN + 1023) / 1024; // 98
    const int GY = (NN + 127) / 128;     // 782
    const int WG = (NN * 32 + 255) / 256;

    // --- fork: CSR build + transposes on side stream, overlapped with G1 ---
    cudaEventRecord(evFork, 0);
    cudaStreamWaitEvent(s2, evFork, 0);

    k_zero_deg<<<(NN + 255) / 256, 256, 0, s2>>>();
    k_hist<<<(NE + 255) / 256, 256, 0, s2>>>(dst);
    k_scan1<<<NBLK, 1024, 0, s2>>>();
    k_scan2<<<1, 128, 0, s2>>>();
    k_scan3<<<(NN + 255) / 256, 256, 0, s2>>>();
    k_scatter<<<(NE + 255) / 256, 256, 0, s2>>>(src, dst);
    k_transpose_W1<<<(IND * HIDD + 255) / 256, 256, 0, s2>>>(W1);
    k_transpose_W2<<<(HIDD * OUTD + 255) / 256, 256, 0, s2>>>(W2);
    cudaEventRecord(evJoin, s2);

    // --- main stream: G1 + logits (independent of CSR) ---
    k_gemm_tc<4, 2, 2, 8, false><<<dim3(1, GY), 256>>>(x, W1, p_xs1, NN, HIDD, IND);
    k_logits<<<WG, 256>>>(a_src, a_dst);

    // --- join: weights needs CSR + logits ---
    cudaStreamWaitEvent(0, evJoin, 0);
    k_weights<<<WG, 256>>>();

    // --- agg1: h1 = elu(A * xs1) ---
    k_gather_elu<<<WG, 256>>>(p_xs1, p_h1);

    // --- G2: h2 = h1 @ W2  [100k,128]@[128,32] ---
    k_gemm_tc<8, 1, 1, 4, false><<<dim3(1, GY), 256>>>(p_h1, W2, h2, NN, OUTD, HIDD);

    // --- agg2': A * h2  (32-wide gather; aggregation commutes with @W2^T) ---
    k_gather32<<<WG, 256>>>(h2, p_agg2);

    // --- G3: h3 = elu(agg2' @ W2^T)  [100k,32]@[32,128], fused ELU ---
    k_gemm_tc<4, 2, 2, 8, true><<<dim3(1, GY), 256>>>(p_agg2, p_W2T, p_h3, NN, HIDD, OUTD);

    // --- G4: h4 = h3 @ W1^T  [100k,128]@[128,256] ---
    k_gemm_tc<4, 2, 2, 8, false><<<dim3(2, GY), 256>>>(p_h3, p_W1T, h4, NN, IND, HIDD);
}